// round 3
// baseline (speedup 1.0000x reference)
#include <cuda_runtime.h>

// MPSLayer, fully fused single kernel.
//   out[b,o]  = s[b]*v[o] + bias[o]
//   s[b]      = prod_n x[b,n]
//   u         = ones^T @ core_0 @ ... @ core_255
//   Psum[r,o] = sum_l proj[r,l,o]
//   v[o]      = sum_r u[r]*Psum[r,o]
//
// One launch; cross-block deps via fence + atomic counters + spin.
// Grid 256 x 256, all blocks co-resident (wave 1), so spinning is safe.

#define DD      32
#define N_IN    256
#define BATCH   1024
#define OUT_DIM 512

__device__ __align__(16) float g_D[64 * DD * DD];   // level-1 products
__device__ __align__(16) float g_E[8 * DD * DD];    // level-2 products
__device__ __align__(16) float g_s[BATCH];
__device__ __align__(16) float g_Psum[DD * OUT_DIM];
__device__ __align__(16) float g_v[OUT_DIM];

// progress counters (zero at load; restored to zero before kernel exit)
__device__ int g_cnt_D, g_cnt_E, g_cnt_P, g_cnt_S, g_flag_v, g_cnt_done;

__device__ __forceinline__ void block_spin_ge(int* cnt, int target) {
    if (threadIdx.x == 0) {
        while (atomicAdd(cnt, 0) < target) __nanosleep(64);
    }
    __syncthreads();
    __threadfence();   // order subsequent data loads after observed release
}

// ---------------------------------------------------------------------------
// 32x32x32 matmul step: C = A(smem) @ B(smem); thread (l=tid>>3,q=tid&7)
// computes C[l][4q..4q+3].
// ---------------------------------------------------------------------------
__device__ __forceinline__ float4 mm_step(const float* __restrict__ A,
                                          const float* __restrict__ B,
                                          int l, int q) {
    const float4* B4 = reinterpret_cast<const float4*>(B);
    float4 acc = make_float4(0.f, 0.f, 0.f, 0.f);
    #pragma unroll
    for (int k = 0; k < DD; ++k) {
        float a = A[l * DD + k];
        float4 b = B4[k * 8 + q];
        acc.x = fmaf(a, b.x, acc.x);
        acc.y = fmaf(a, b.y, acc.y);
        acc.z = fmaf(a, b.z, acc.z);
        acc.w = fmaf(a, b.w, acc.w);
    }
    return acc;
}

// Chain NMAT 32x32 matrices from global src -> global dst. 256 threads.
// sm must hold 3*1024 floats (A ping/pong + streamed B with LDG prefetch).
template <int NMAT>
__device__ __forceinline__ void mm_chain(const float* __restrict__ src,
                                         float* __restrict__ dst,
                                         float* __restrict__ sm) {
    float* sA[2] = { sm, sm + DD * DD };
    float* sB = sm + 2 * DD * DD;
    int tid = threadIdx.x;
    int l = tid >> 3, q = tid & 7;

    const float4* src4 = reinterpret_cast<const float4*>(src);
    reinterpret_cast<float4*>(sA[0])[tid] = src4[tid];        // M0
    reinterpret_cast<float4*>(sB)[tid]    = src4[256 + tid];  // M1
    int cur = 0;
    #pragma unroll
    for (int j = 1; j < NMAT; ++j) {
        float4 nb;
        if (j < NMAT - 1) nb = src4[(j + 1) * 256 + tid];     // prefetch M_{j+1}
        __syncthreads();
        float4 acc = mm_step(sA[cur], sB, l, q);
        __syncthreads();
        if (j < NMAT - 1) {
            reinterpret_cast<float4*>(sA[cur ^ 1])[tid] = acc;
            reinterpret_cast<float4*>(sB)[tid] = nb;
            cur ^= 1;
        } else {
            reinterpret_cast<float4*>(dst)[tid] = acc;
        }
    }
}

// ---------------------------------------------------------------------------
__global__ void __launch_bounds__(256) fused_mps(
    const float* __restrict__ x, const float* __restrict__ cores,
    const float* __restrict__ proj, const float* __restrict__ bias,
    float* __restrict__ out) {

    __shared__ float sm[8 * DD * DD];   // 32 KB: mm buffers / g_E staging
    __shared__ float sU[DD];
    int tid = threadIdx.x;
    int blk = blockIdx.x;

    // ---- phase 1 -----------------------------------------------------------
    if (blk < 64) {
        // g_D[blk] = cores[4b] @ cores[4b+1] @ cores[4b+2] @ cores[4b+3]
        mm_chain<4>(cores + (size_t)blk * 4 * DD * DD, g_D + blk * DD * DD, sm);
        __threadfence();
        if (tid == 0) atomicAdd(&g_cnt_D, 1);

        if (blk < 8) {
            // ---- level 2: g_E[blk] = g_D[8b] @ ... @ g_D[8b+7]
            block_spin_ge(&g_cnt_D, 64);
            mm_chain<8>(g_D + (size_t)blk * 8 * DD * DD, g_E + blk * DD * DD, sm);
            __threadfence();
            if (tid == 0) atomicAdd(&g_cnt_E, 1);
        }
        if (blk == 0) {
            // ---- level 3: u then v
            block_spin_ge(&g_cnt_E, 8);
            block_spin_ge(&g_cnt_P, 64);
            // stage all of g_E (32 KB) into smem
            const float4* e4 = reinterpret_cast<const float4*>(g_E);
            float4* sm4 = reinterpret_cast<float4*>(sm);
            #pragma unroll
            for (int i = 0; i < 8; ++i) sm4[tid + i * 256] = e4[tid + i * 256];
            __syncthreads();
            if (tid < DD) {
                float u = 1.f;
                #pragma unroll
                for (int n = 0; n < 8; ++n) {
                    const float* d = sm + n * DD * DD;
                    float a0 = 0.f, a1 = 0.f, a2 = 0.f, a3 = 0.f;
                    #pragma unroll
                    for (int k = 0; k < DD; k += 4) {
                        a0 = fmaf(__shfl_sync(0xffffffffu, u, k + 0), d[(k + 0) * DD + tid], a0);
                        a1 = fmaf(__shfl_sync(0xffffffffu, u, k + 1), d[(k + 1) * DD + tid], a1);
                        a2 = fmaf(__shfl_sync(0xffffffffu, u, k + 2), d[(k + 2) * DD + tid], a2);
                        a3 = fmaf(__shfl_sync(0xffffffffu, u, k + 3), d[(k + 3) * DD + tid], a3);
                    }
                    u = (a0 + a1) + (a2 + a3);
                }
                sU[tid] = u;
            }
            __syncthreads();
            // v[o] = sum_r sU[r] * Psum[r,o]; 256 threads x 2 outputs
            #pragma unroll
            for (int h = 0; h < 2; ++h) {
                int o = tid + h * 256;
                float acc = 0.f;
                #pragma unroll
                for (int r = 0; r < DD; ++r)
                    acc = fmaf(sU[r], g_Psum[r * OUT_DIM + o], acc);
                g_v[o] = acc;
            }
            __threadfence();
            __syncthreads();
            if (tid == 0) {
                // all readers of these counters have provably passed
                g_cnt_D = 0; g_cnt_E = 0; g_cnt_P = 0;
                __threadfence();
                atomicExch(&g_flag_v, 1);   // release v
            }
        }
    } else if (blk < 192) {
        // ---- s[b]: 8 rows per block, one warp per row
        int w = tid >> 5, e = tid & 31;
        int b = (blk - 64) * 8 + w;
        const float* row = x + (size_t)b * N_IN;
        float p = 1.f;
        #pragma unroll
        for (int i = 0; i < N_IN / DD; ++i) p *= row[e + i * DD];
        #pragma unroll
        for (int off = 16; off; off >>= 1)
            p *= __shfl_xor_sync(0xffffffffu, p, off);
        if (e == 0) g_s[b] = p;
        __threadfence();
        __syncthreads();
        if (tid == 0) atomicAdd(&g_cnt_S, 1);
    } else {
        // ---- Psum[r, o-half]: block p -> r = p/2, half = p&1
        int p = blk - 192;
        int r = p >> 1;
        int o = (p & 1) * 256 + tid;
        const float* base = proj + (size_t)r * DD * OUT_DIM + o;
        float acc = 0.f;
        #pragma unroll
        for (int l = 0; l < DD; ++l) acc += base[l * OUT_DIM];
        g_Psum[r * OUT_DIM + o] = acc;
        __threadfence();
        if (tid == 0) atomicAdd(&g_cnt_P, 1);
    }

    // ---- epilogue: out[b,o] = s[b]*v[o] + bias[o] ---------------------------
    block_spin_ge(&g_flag_v, 1);
    block_spin_ge(&g_cnt_S, 128);

    int o4  = tid & 127;                 // float4 column index
    int sub = tid >> 7;                  // 0..1
    float4 v  = reinterpret_cast<const float4*>(g_v)[o4];
    float4 bi = reinterpret_cast<const float4*>(bias)[o4];
    float4* out4 = reinterpret_cast<float4*>(out);
    int b0 = blk * 4;
    #pragma unroll
    for (int i = 0; i < 2; ++i) {
        int b = b0 + i * 2 + sub;
        float s = g_s[b];
        float4 o;
        o.x = fmaf(s, v.x, bi.x);
        o.y = fmaf(s, v.y, bi.y);
        o.z = fmaf(s, v.z, bi.z);
        o.w = fmaf(s, v.w, bi.w);
        out4[(size_t)b * (OUT_DIM / 4) + o4] = o;
    }

    // ---- last block out resets the remaining flags for the next replay -----
    __syncthreads();
    if (tid == 0) {
        int old = atomicAdd(&g_cnt_done, 1);
        if (old == 255) {
            atomicExch(&g_cnt_S, 0);
            atomicExch(&g_flag_v, 0);
            atomicExch(&g_cnt_done, 0);
        }
    }
}

// ---------------------------------------------------------------------------
extern "C" void kernel_launch(void* const* d_in, const int* in_sizes, int n_in,
                              void* d_out, int out_size) {
    const float* x     = (const float*)d_in[0];
    const float* cores = (const float*)d_in[1];
    const float* proj  = (const float*)d_in[2];
    const float* bias  = (const float*)d_in[3];
    float* out = (float*)d_out;

    fused_mps<<<256, 256>>>(x, cores, proj, bias, out);
}

// round 4
// speedup vs baseline: 1.2003x; 1.2003x over previous
#include <cuda_runtime.h>

// MPSLayer, fused single kernel, acquire/release sync (no threadfence/CCTL).
//   out[b,o]  = s[b]*v[o] + bias[o]
//   s[b]      = prod_n x[b,n]
//   u         = ones^T @ core_0 @ ... @ core_255
//   Psum[r,o] = sum_l proj[r,l,o]
//   v[o]      = sum_r u[r]*Psum[r,o]
//
// Chain tree: 64 blocks x (product of 4 cores)  -> g_D   [depth 3]
//             16 blocks x (product of 4 g_D)    -> g_E   [depth 3]
//             block 0: 16-step vector chain     -> u, v  [depth 16 cheap]
// Grid 256x256, all co-resident; spins are safe.

#define DD      32
#define N_IN    256
#define BATCH   1024
#define OUT_DIM 512

__device__ __align__(16) float g_D[64 * DD * DD];
__device__ __align__(16) float g_E[16 * DD * DD];
__device__ __align__(16) float g_s[BATCH];
__device__ __align__(16) float g_Psum[DD * OUT_DIM];
__device__ __align__(16) float g_v[OUT_DIM];

__device__ int g_cnt_D4[16];   // per level-2-group completion counters
__device__ int g_cnt_E, g_cnt_P, g_cnt_S, g_flag_v, g_cnt_done;

// ---- sync primitives: per-op semantics, no L1-flushing fences --------------
__device__ __forceinline__ int ld_acq(const int* p) {
    int v;
    asm volatile("ld.acquire.gpu.global.b32 %0, [%1];" : "=r"(v) : "l"(p) : "memory");
    return v;
}
__device__ __forceinline__ void red_rel_add(int* p, int v) {
    asm volatile("red.release.gpu.global.add.s32 [%0], %1;" :: "l"(p), "r"(v) : "memory");
}
__device__ __forceinline__ void st_relaxed(int* p, int v) {
    asm volatile("st.relaxed.gpu.global.b32 [%0], %1;" :: "l"(p), "r"(v) : "memory");
}
// all threads of block wait until *cnt >= target
__device__ __forceinline__ void spin_ge(int* cnt, int target) {
    if (threadIdx.x == 0) {
        while (ld_acq(cnt) < target) { }
    }
    __syncthreads();
}

// ---------------------------------------------------------------------------
// 32x32x32 matmul step: C = A(smem) @ B(smem); thread (l=tid>>3, q=tid&7)
// computes C[l][4q..4q+3].
// ---------------------------------------------------------------------------
__device__ __forceinline__ float4 mm_step(const float* __restrict__ A,
                                          const float* __restrict__ B,
                                          int l, int q) {
    const float4* B4 = reinterpret_cast<const float4*>(B);
    float4 acc = make_float4(0.f, 0.f, 0.f, 0.f);
    #pragma unroll
    for (int k = 0; k < DD; ++k) {
        float a = A[l * DD + k];
        float4 b = B4[k * 8 + q];
        acc.x = fmaf(a, b.x, acc.x);
        acc.y = fmaf(a, b.y, acc.y);
        acc.z = fmaf(a, b.z, acc.z);
        acc.w = fmaf(a, b.w, acc.w);
    }
    return acc;
}

// Chain 4 matrices src[0..3] -> dst. 256 threads. sm: 3*1024 floats.
__device__ __forceinline__ void mm_chain4(const float* __restrict__ src,
                                          float* __restrict__ dst,
                                          float* __restrict__ sm) {
    float* sA0 = sm;
    float* sA1 = sm + DD * DD;
    float* sB  = sm + 2 * DD * DD;
    int tid = threadIdx.x;
    int l = tid >> 3, q = tid & 7;

    const float4* src4 = reinterpret_cast<const float4*>(src);
    reinterpret_cast<float4*>(sA0)[tid] = src4[tid];        // M0
    reinterpret_cast<float4*>(sB)[tid]  = src4[256 + tid];  // M1
    float4 p2 = src4[512 + tid];                            // prefetch M2
    float4 p3 = src4[768 + tid];                            // prefetch M3
    __syncthreads();
    float4 acc = mm_step(sA0, sB, l, q);                    // M0@M1
    __syncthreads();
    reinterpret_cast<float4*>(sA1)[tid] = acc;
    reinterpret_cast<float4*>(sB)[tid]  = p2;
    __syncthreads();
    acc = mm_step(sA1, sB, l, q);                           // @M2
    __syncthreads();
    reinterpret_cast<float4*>(sA0)[tid] = acc;
    reinterpret_cast<float4*>(sB)[tid]  = p3;
    __syncthreads();
    acc = mm_step(sA0, sB, l, q);                           // @M3
    reinterpret_cast<float4*>(dst)[tid] = acc;
    __syncthreads();                                        // all stores issued
}

// one vector-chain step: u <- u @ d (d = 32 per-lane column values)
__device__ __forceinline__ float chain_step(float u, const float* d) {
    float a0 = 0.f, a1 = 0.f, a2 = 0.f, a3 = 0.f;
    #pragma unroll
    for (int k = 0; k < DD; k += 4) {
        a0 = fmaf(__shfl_sync(0xffffffffu, u, k + 0), d[k + 0], a0);
        a1 = fmaf(__shfl_sync(0xffffffffu, u, k + 1), d[k + 1], a1);
        a2 = fmaf(__shfl_sync(0xffffffffu, u, k + 2), d[k + 2], a2);
        a3 = fmaf(__shfl_sync(0xffffffffu, u, k + 3), d[k + 3], a3);
    }
    return (a0 + a1) + (a2 + a3);
}

// ---------------------------------------------------------------------------
__global__ void __launch_bounds__(256) fused_mps(
    const float* __restrict__ x, const float* __restrict__ cores,
    const float* __restrict__ proj, const float* __restrict__ bias,
    float* __restrict__ out) {

    __shared__ float sm[3 * DD * DD];
    __shared__ float sU[DD];
    int tid = threadIdx.x;
    int blk = blockIdx.x;

    if (blk < 64) {
        // ---- level 1: g_D[blk] = cores[4blk] @ ... @ cores[4blk+3]
        mm_chain4(cores + (size_t)blk * 4 * DD * DD, g_D + blk * DD * DD, sm);
        if (tid == 0) red_rel_add(&g_cnt_D4[blk >> 2], 1);

        if (blk < 16) {
            // ---- level 2: g_E[blk] = g_D[4blk] @ ... @ g_D[4blk+3]
            spin_ge(&g_cnt_D4[blk], 4);
            if (tid == 0) st_relaxed(&g_cnt_D4[blk], 0);   // unique reader: reset
            mm_chain4(g_D + (size_t)blk * 4 * DD * DD, g_E + blk * DD * DD, sm);
            if (tid == 0) red_rel_add(&g_cnt_E, 1);
        }
        if (blk == 0) {
            // ---- level 3: u = ones^T E0..E15 ; v = u^T Psum
            spin_ge(&g_cnt_E, 16);
            if (tid == 0) st_relaxed(&g_cnt_E, 0);
            if (tid < DD) {
                int lane = tid;
                float u = 1.f;
                float cur[DD], nxt[DD];
                #pragma unroll
                for (int k = 0; k < DD; ++k) cur[k] = g_E[k * DD + lane];
                #pragma unroll
                for (int n = 0; n < 16; n += 2) {
                    const float* p1 = g_E + (n + 1) * DD * DD;
                    #pragma unroll
                    for (int k = 0; k < DD; ++k) nxt[k] = p1[k * DD + lane];
                    u = chain_step(u, cur);
                    if (n + 2 < 16) {
                        const float* p2 = g_E + (n + 2) * DD * DD;
                        #pragma unroll
                        for (int k = 0; k < DD; ++k) cur[k] = p2[k * DD + lane];
                    }
                    u = chain_step(u, nxt);
                }
                sU[lane] = u;
            }
            spin_ge(&g_cnt_P, 64);                // also syncs sU for the block
            if (tid == 0) st_relaxed(&g_cnt_P, 0);
            #pragma unroll
            for (int h = 0; h < 2; ++h) {
                int o = tid + h * 256;
                float acc = 0.f;
                #pragma unroll
                for (int r = 0; r < DD; ++r)
                    acc = fmaf(sU[r], g_Psum[r * OUT_DIM + o], acc);
                g_v[o] = acc;
            }
            __syncthreads();
            if (tid == 0) red_rel_add(&g_flag_v, 1);
        }
    } else if (blk < 192) {
        // ---- s[b]: 8 rows per block, one warp per row
        int w = tid >> 5, e = tid & 31;
        int b = (blk - 64) * 8 + w;
        const float* row = x + (size_t)b * N_IN;
        float p = 1.f;
        #pragma unroll
        for (int i = 0; i < N_IN / DD; ++i) p *= row[e + i * DD];
        #pragma unroll
        for (int off = 16; off; off >>= 1)
            p *= __shfl_xor_sync(0xffffffffu, p, off);
        if (e == 0) g_s[b] = p;
        __syncthreads();
        if (tid == 0) red_rel_add(&g_cnt_S, 1);
    } else {
        // ---- Psum[r, o-half]
        int p = blk - 192;
        int r = p >> 1;
        int o = (p & 1) * 256 + tid;
        const float* base = proj + (size_t)r * DD * OUT_DIM + o;
        float acc = 0.f;
        #pragma unroll
        for (int l = 0; l < DD; ++l) acc += base[l * OUT_DIM];
        g_Psum[r * OUT_DIM + o] = acc;
        __syncthreads();
        if (tid == 0) red_rel_add(&g_cnt_P, 1);
    }

    // ---- epilogue: out[b,o] = s[b]*v[o] + bias[o] ---------------------------
    spin_ge(&g_flag_v, 1);
    spin_ge(&g_cnt_S, 128);

    int o4  = tid & 127;
    int sub = tid >> 7;
    float4 v  = reinterpret_cast<const float4*>(g_v)[o4];
    float4 bi = reinterpret_cast<const float4*>(bias)[o4];
    float4* out4 = reinterpret_cast<float4*>(out);
    int b0 = blk * 4;
    #pragma unroll
    for (int i = 0; i < 2; ++i) {
        int b = b0 + i * 2 + sub;
        float s = g_s[b];
        float4 o;
        o.x = fmaf(s, v.x, bi.x);
        o.y = fmaf(s, v.y, bi.y);
        o.z = fmaf(s, v.z, bi.z);
        o.w = fmaf(s, v.w, bi.w);
        out4[(size_t)b * (OUT_DIM / 4) + o4] = o;
    }

    // ---- last block resets shared flags for next graph replay --------------
    __syncthreads();
    if (tid == 0) {
        int old = atomicAdd(&g_cnt_done, 1);
        if (old == 255) {
            st_relaxed(&g_cnt_S, 0);
            st_relaxed(&g_flag_v, 0);
            st_relaxed(&g_cnt_done, 0);
        }
    }
}

// ---------------------------------------------------------------------------
extern "C" void kernel_launch(void* const* d_in, const int* in_sizes, int n_in,
                              void* d_out, int out_size) {
    const float* x     = (const float*)d_in[0];
    const float* cores = (const float*)d_in[1];
    const float* proj  = (const float*)d_in[2];
    const float* bias  = (const float*)d_in[3];
    float* out = (float*)d_out;

    fused_mps<<<256, 256>>>(x, cores, proj, bias, out);
}

// round 5
// speedup vs baseline: 1.3364x; 1.1134x over previous
#include <cuda_runtime.h>

// MPSLayer, fused single kernel. acquire/release sync, cp.async level-3 pipe,
// register-resident 32x32 matmul chains.
//   out[b,o]  = s[b]*v[o] + bias[o]
//   s[b]      = prod_n x[b,n]
//   u         = ones^T @ core_0 @ ... @ core_255
//   Psum[r,o] = sum_l proj[r,l,o]
//   v[o]      = sum_r u[r]*Psum[r,o]
// Tree: 64 blocks ∏4 cores -> g_D ; 16 blocks ∏4 g_D -> g_E ;
//       block 0: 16-step vector chain (cp.async smem ring) -> u -> v.

#define DD      32
#define N_IN    256
#define BATCH   1024
#define OUT_DIM 512

__device__ __align__(16) float g_D[64 * DD * DD];
__device__ __align__(16) float g_E[16 * DD * DD];
__device__ __align__(16) float g_s[BATCH];
__device__ __align__(16) float g_Psum[DD * OUT_DIM];
__device__ __align__(16) float g_v[OUT_DIM];

__device__ int g_cnt_D4[16];
__device__ int g_cnt_E, g_cnt_P, g_cnt_S, g_flag_v, g_cnt_done;

// ---- sync primitives --------------------------------------------------------
__device__ __forceinline__ int ld_acq(const int* p) {
    int v;
    asm volatile("ld.acquire.gpu.global.b32 %0, [%1];" : "=r"(v) : "l"(p) : "memory");
    return v;
}
__device__ __forceinline__ void red_rel_add(int* p, int v) {
    asm volatile("red.release.gpu.global.add.s32 [%0], %1;" :: "l"(p), "r"(v) : "memory");
}
__device__ __forceinline__ void st_relaxed(int* p, int v) {
    asm volatile("st.relaxed.gpu.global.b32 [%0], %1;" :: "l"(p), "r"(v) : "memory");
}
__device__ __forceinline__ void spin_ge(int* cnt, int target) {
    if (threadIdx.x == 0) {
        while (ld_acq(cnt) < target) { }
    }
    __syncthreads();
}

// ---- cp.async ---------------------------------------------------------------
__device__ __forceinline__ void cpa16(unsigned dst, const float* src) {
    asm volatile("cp.async.ca.shared.global [%0], [%1], 16;" :: "r"(dst), "l"(src));
}
#define CP_COMMIT() asm volatile("cp.async.commit_group;" ::: "memory")
#define CP_WAIT(n)  asm volatile("cp.async.wait_group %0;" :: "n"(n) : "memory")

// ---------------------------------------------------------------------------
// Register-resident 32x32 matmul step: thread owns P[l][4q..4q+3] (l=tid>>3,
// q=tid&7). New P = P @ B(smem). Row P[l][k] gathered by shfl from the 8 lanes
// of the same row group (lane & 24).
// ---------------------------------------------------------------------------
__device__ __forceinline__ float4 mm_step_reg(float4 p, const float4* __restrict__ B4,
                                              int lane, int q) {
    float4 acc = make_float4(0.f, 0.f, 0.f, 0.f);
    int grp = lane & 24;
    #pragma unroll
    for (int j = 0; j < 8; ++j) {
        float a; float4 b;
        a = __shfl_sync(0xffffffffu, p.x, grp + j);
        b = B4[(4 * j + 0) * 8 + q];
        acc.x = fmaf(a, b.x, acc.x); acc.y = fmaf(a, b.y, acc.y);
        acc.z = fmaf(a, b.z, acc.z); acc.w = fmaf(a, b.w, acc.w);
        a = __shfl_sync(0xffffffffu, p.y, grp + j);
        b = B4[(4 * j + 1) * 8 + q];
        acc.x = fmaf(a, b.x, acc.x); acc.y = fmaf(a, b.y, acc.y);
        acc.z = fmaf(a, b.z, acc.z); acc.w = fmaf(a, b.w, acc.w);
        a = __shfl_sync(0xffffffffu, p.z, grp + j);
        b = B4[(4 * j + 2) * 8 + q];
        acc.x = fmaf(a, b.x, acc.x); acc.y = fmaf(a, b.y, acc.y);
        acc.z = fmaf(a, b.z, acc.z); acc.w = fmaf(a, b.w, acc.w);
        a = __shfl_sync(0xffffffffu, p.w, grp + j);
        b = B4[(4 * j + 3) * 8 + q];
        acc.x = fmaf(a, b.x, acc.x); acc.y = fmaf(a, b.y, acc.y);
        acc.z = fmaf(a, b.z, acc.z); acc.w = fmaf(a, b.w, acc.w);
    }
    return acc;
}

// Product of 4 consecutive 32x32 matrices at src. Result returned in-reg
// (thread's float4 tile). sB0/sB1: two 4KB smem buffers. 256 threads.
__device__ __forceinline__ float4 mm_chain4_reg(const float4* __restrict__ src4,
                                                float4* sB0, float4* sB1) {
    int tid = threadIdx.x, lane = tid & 31, q = tid & 7;
    float4 p  = src4[tid];          // M0 tile
    float4 b1 = src4[256 + tid];    // prefetch M1..M3 (MLP=4)
    float4 b2 = src4[512 + tid];
    float4 b3 = src4[768 + tid];
    sB0[tid] = b1; __syncthreads();
    p = mm_step_reg(p, sB0, lane, q);
    sB1[tid] = b2; __syncthreads();
    p = mm_step_reg(p, sB1, lane, q);
    sB0[tid] = b3; __syncthreads();   // safe: all threads read sB0 before this sync's predecessor
    p = mm_step_reg(p, sB0, lane, q);
    return p;
}

// one vector-chain step from smem: u <- u @ D, lane owns column `lane`
__device__ __forceinline__ float chain_step_smem(float u, const float* __restrict__ d,
                                                 int lane) {
    float a0 = 0.f, a1 = 0.f, a2 = 0.f, a3 = 0.f;
    #pragma unroll
    for (int k = 0; k < DD; k += 4) {
        a0 = fmaf(__shfl_sync(0xffffffffu, u, k + 0), d[(k + 0) * DD + lane], a0);
        a1 = fmaf(__shfl_sync(0xffffffffu, u, k + 1), d[(k + 1) * DD + lane], a1);
        a2 = fmaf(__shfl_sync(0xffffffffu, u, k + 2), d[(k + 2) * DD + lane], a2);
        a3 = fmaf(__shfl_sync(0xffffffffu, u, k + 3), d[(k + 3) * DD + lane], a3);
    }
    return (a0 + a1) + (a2 + a3);
}

// ---------------------------------------------------------------------------
__global__ void __launch_bounds__(256) fused_mps(
    const float* __restrict__ x, const float* __restrict__ cores,
    const float* __restrict__ proj, const float* __restrict__ bias,
    float* __restrict__ out) {

    __shared__ __align__(16) float sm[4 * 1024];   // 16KB: mm B-buffers / cp ring
    __shared__ float sU[DD];
    int tid = threadIdx.x;
    int blk = blockIdx.x;
    int lane = tid & 31;

    // preload epilogue constants early (independent of everything)
    int o4 = tid & 127;
    float4 bi = reinterpret_cast<const float4*>(bias)[o4];

    float4* sB0 = reinterpret_cast<float4*>(sm);
    float4* sB1 = reinterpret_cast<float4*>(sm + 1024);

    if (blk < 64) {
        // ---- level 1: g_D[blk] = cores[4blk..4blk+3] product
        float4 p = mm_chain4_reg(
            reinterpret_cast<const float4*>(cores) + (size_t)blk * 1024, sB0, sB1);
        reinterpret_cast<float4*>(g_D)[blk * 256 + tid] = p;
        if (tid == 0) red_rel_add(&g_cnt_D4[blk >> 2], 1);

        if (blk < 16) {
            // ---- level 2: E[blk] = g_D[4blk..4blk+3] product
            spin_ge(&g_cnt_D4[blk], 4);
            if (tid == 0) st_relaxed(&g_cnt_D4[blk], 0);
            float4 e = mm_chain4_reg(
                reinterpret_cast<const float4*>(g_D) + (size_t)blk * 1024, sB0, sB1);
            if (blk > 0) {
                reinterpret_cast<float4*>(g_E)[blk * 256 + tid] = e;
                if (tid == 0) red_rel_add(&g_cnt_E, 1);
            } else {
                // E0 consumed only by this block: place straight into ring stage 0
                __syncthreads();                     // mm reads of sB0 done
                reinterpret_cast<float4*>(sm)[tid] = e;
            }
        }
        if (blk == 0) {
            // Psum is ready long before the chain: sync + prefetch columns
            spin_ge(&g_cnt_P, 64);
            if (tid == 0) st_relaxed(&g_cnt_P, 0);
            float pc0[DD], pc1[DD];
            #pragma unroll
            for (int r = 0; r < DD; ++r) pc0[r] = g_Psum[r * OUT_DIM + tid];
            #pragma unroll
            for (int r = 0; r < DD; ++r) pc1[r] = g_Psum[r * OUT_DIM + tid + 256];

            spin_ge(&g_cnt_E, 15);                  // E1..E15 present (E0 in smem)

            if (tid < DD) {                          // warp 0: vector chain
                unsigned smb = (unsigned)__cvta_generic_to_shared(sm) + (lane << 4);
                const float* gsrc = g_E + lane * 4;
                // prime stages 1..3
                #pragma unroll
                for (int m = 1; m <= 3; ++m) {
                    unsigned d = smb + ((m & 3) << 12);
                    const float* s = gsrc + m * 1024;
                    #pragma unroll
                    for (int i = 0; i < 8; ++i) cpa16(d + (i << 9), s + i * 128);
                    CP_COMMIT();
                }
                float u = 1.f;
                #pragma unroll
                for (int n = 0; n < 16; ++n) {
                    if (n >= 1) {
                        if (n <= 13)      CP_WAIT(2);
                        else if (n == 14) CP_WAIT(1);
                        else              CP_WAIT(0);
                        __syncwarp();
                    }
                    if (n + 3 >= 4 && n + 3 < 16) {  // issue stage n+3
                        int m = n + 3;
                        unsigned d = smb + ((m & 3) << 12);
                        const float* s = gsrc + m * 1024;
                        #pragma unroll
                        for (int i = 0; i < 8; ++i) cpa16(d + (i << 9), s + i * 128);
                        CP_COMMIT();
                    }
                    u = chain_step_smem(u, sm + ((n & 3) << 10), lane);
                }
                sU[lane] = u;
            }
            __syncthreads();
            // v = u^T Psum from prefetched registers
            float a0 = 0.f, a1 = 0.f;
            #pragma unroll
            for (int r = 0; r < DD; ++r) {
                float ur = sU[r];
                a0 = fmaf(ur, pc0[r], a0);
                a1 = fmaf(ur, pc1[r], a1);
            }
            g_v[tid]       = a0;
            g_v[tid + 256] = a1;
            __syncthreads();
            if (tid == 0) { st_relaxed(&g_cnt_E, 0); red_rel_add(&g_flag_v, 1); }
        }
    } else if (blk < 192) {
        // ---- s[b]: 8 rows per block, one warp per row
        int w = tid >> 5;
        int b = (blk - 64) * 8 + w;
        const float* row = x + (size_t)b * N_IN;
        float pr = 1.f;
        #pragma unroll
        for (int i = 0; i < N_IN / DD; ++i) pr *= row[lane + i * DD];
        #pragma unroll
        for (int off = 16; off; off >>= 1)
            pr *= __shfl_xor_sync(0xffffffffu, pr, off);
        if (lane == 0) g_s[b] = pr;
        __syncthreads();
        if (tid == 0) red_rel_add(&g_cnt_S, 1);
    } else {
        // ---- Psum[r, half]
        int p = blk - 192;
        int r = p >> 1;
        int o = (p & 1) * 256 + tid;
        const float* base = proj + (size_t)r * DD * OUT_DIM + o;
        float acc = 0.f;
        #pragma unroll
        for (int l = 0; l < DD; ++l) acc += base[l * OUT_DIM];
        g_Psum[r * OUT_DIM + o] = acc;
        __syncthreads();
        if (tid == 0) red_rel_add(&g_cnt_P, 1);
    }

    // ---- epilogue: out[b,o] = s[b]*v[o] + bias[o] ---------------------------
    spin_ge(&g_flag_v, 1);
    spin_ge(&g_cnt_S, 128);

    int sub = tid >> 7;
    float4 v = reinterpret_cast<const float4*>(g_v)[o4];
    float4* out4 = reinterpret_cast<float4*>(out);
    int b0 = blk * 4;
    #pragma unroll
    for (int i = 0; i < 2; ++i) {
        int b = b0 + i * 2 + sub;
        float s = g_s[b];
        float4 o;
        o.x = fmaf(s, v.x, bi.x);
        o.y = fmaf(s, v.y, bi.y);
        o.z = fmaf(s, v.z, bi.z);
        o.w = fmaf(s, v.w, bi.w);
        out4[(size_t)b * (OUT_DIM / 4) + o4] = o;
    }

    // ---- last block resets shared flags for next graph replay --------------
    __syncthreads();
    if (tid == 0) {
        int old = atomicAdd(&g_cnt_done, 1);
        if (old == 255) {
            st_relaxed(&g_cnt_S, 0);
            st_relaxed(&g_flag_v, 0);
            st_relaxed(&g_cnt_done, 0);
        }
    }
}

// ---------------------------------------------------------------------------
extern "C" void kernel_launch(void* const* d_in, const int* in_sizes, int n_in,
                              void* d_out, int out_size) {
    const float* x     = (const float*)d_in[0];
    const float* cores = (const float*)d_in[1];
    const float* proj  = (const float*)d_in[2];
    const float* bias  = (const float*)d_in[3];
    float* out = (float*)d_out;

    fused_mps<<<256, 256>>>(x, cores, proj, bias, out);
}